// round 16
// baseline (speedup 1.0000x reference)
#include <cuda_runtime.h>
#include <cstring>

#define DINLINE __device__ __forceinline__

DINLINE float2 ffma2(float2 a, float2 b, float2 c) {
    unsigned long long au, bu, cu, ru;
    memcpy(&au, &a, 8); memcpy(&bu, &b, 8); memcpy(&cu, &c, 8);
    asm("fma.rn.f32x2 %0, %1, %2, %3;" : "=l"(ru) : "l"(au), "l"(bu), "l"(cu));
    float2 r; memcpy(&r, &ru, 8); return r;
}
DINLINE float2 fadd2(float2 a, float2 b) {
    unsigned long long au, bu, ru;
    memcpy(&au, &a, 8); memcpy(&bu, &b, 8);
    asm("add.rn.f32x2 %0, %1, %2;" : "=l"(ru) : "l"(au), "l"(bu));
    float2 r; memcpy(&r, &ru, 8); return r;
}

// ---------- scratch ----------
__device__ unsigned long long g_grid64[32 * 64 * 64];            // 1 MB bitmask
// x1: [b][iz32][ch16][iy32][36]  even x(16) 0..15, odd_shifted(17) 16..32, pad
__device__ float g_x1[(size_t)32 * 32 * 16 * 32 * 36];           // 75.5 MB
// x2: [b][iz16][ch32][iy16][20]  even x(8) 0..7, odd_shifted(9) 8..16, pad
__device__ float g_x2[(size_t)32 * 16 * 32 * 16 * 20];           // 21 MB
__device__ float g_feat[(size_t)32 * 32768];                     // [b][c*512 + s]
__device__ float g_w2p[27 * 16 * 32];                            // [tap][in][och]
__device__ float g_w3p[27 * 32 * 64];                            // [tap][in][och]

// ---------- fused: clear grid + repack w2 + repack w3 ----------
__global__ void clear_and_repack(const float* __restrict__ w2,
                                 const float* __restrict__ w3) {
    int i = blockIdx.x * 256 + threadIdx.x;            // 65536 threads
    ((ulonglong2*)g_grid64)[i] = make_ulonglong2(0ull, 0ull);
    if (i < 13824) {
        int tap = i % 27; int r = i / 27;
        int in = r % 16;  int och = r / 16;
        g_w2p[(tap * 16 + in) * 32 + och] = w2[i];
    }
    if (i < 55296) {
        int tap = i % 27; int r = i / 27;
        int in = r % 32;  int och = r / 32;
        g_w3p[(tap * 32 + in) * 64 + och] = w3[i];
    }
}

__global__ void scatter_kernel(const float* __restrict__ pc) {
    int t = blockIdx.x * 256 + threadIdx.x;            // 524288
    float px = pc[t * 3 + 0];
    float py = pc[t * 3 + 1];
    float pz = pc[t * 3 + 2];
    int b = t >> 14;
    int cx = (int)(((px + 1.0f) * 0.5f) * 63.0f); cx = min(max(cx, 0), 63);
    int cy = (int)(((py + 1.0f) * 0.5f) * 63.0f); cy = min(max(cy, 0), 63);
    int cz = (int)(((pz + 1.0f) * 0.5f) * 63.0f); cz = min(max(cz, 0), 63);
    atomicOr(&g_grid64[(b * 64 + cz) * 64 + cy], 1ull << cx);
}

// ---------- conv1 (1->16, 64^3 -> 32^3) ----------
__global__ void __launch_bounds__(512) conv1_kernel(const float* __restrict__ w1,
                                                    const float* __restrict__ b1) {
    __shared__ float2 sw[27 * 8];
    __shared__ float2 sb[8];
    __shared__ float tile[16 * 16 * 36];               // 36.9 KB
    int tid = threadIdx.x;
    int bid = blockIdx.x;                              // 2048 = 32b*32z*2yh
    int yh = bid & 1, z = (bid >> 1) & 31, b = bid >> 6;

    for (int j = tid; j < 216; j += 512) {
        int cp = j & 7, tap = j >> 3;
        sw[j] = make_float2(w1[(2 * cp) * 27 + tap], w1[(2 * cp + 1) * 27 + tap]);
    }
    if (tid < 8) sb[tid] = make_float2(b1[2 * tid], b1[2 * tid + 1]);
    __syncthreads();

    int x = tid & 31, yl = tid >> 5;
    int y = yh * 16 + yl;

    float2 acc[8];
#pragma unroll
    for (int j = 0; j < 8; j++) acc[j] = sb[j];

#pragma unroll 1
    for (int kz = 0; kz < 3; kz++) {
        int iz = 2 * z - 1 + kz;
        if ((unsigned)iz >= 64u) continue;
#pragma unroll 1
        for (int ky = 0; ky < 3; ky++) {
            int iy = 2 * y - 1 + ky;
            if ((unsigned)iy >= 64u) continue;
            unsigned long long m = g_grid64[(b * 64 + iz) * 64 + iy];
            if (!m) continue;
            int tapb = (kz * 3 + ky) * 3;
#pragma unroll 1
            for (int kx = 0; kx < 3; kx++) {
                int ix = 2 * x - 1 + kx;
                if ((unsigned)ix < 64u && ((m >> ix) & 1ull)) {
                    const float2* wv = &sw[(tapb + kx) * 8];
#pragma unroll
                    for (int j = 0; j < 8; j++) acc[j] = fadd2(acc[j], wv[j]);
                }
            }
        }
    }
    int off = (x & 1) ? (16 + ((x + 1) >> 1)) : (x >> 1);
    float* trow = tile + yl * 36;
#pragma unroll
    for (int j = 0; j < 8; j++) {
        trow[(2 * j) * 576 + off]     = fmaxf(acc[j].x, 0.0f);
        trow[(2 * j + 1) * 576 + off] = fmaxf(acc[j].y, 0.0f);
    }
    if (x == 0) {
#pragma unroll
        for (int ch = 0; ch < 16; ch++) trow[ch * 576 + 16] = 0.0f;   // odd_s[0]
    }
    __syncthreads();

    const float4* t4 = (const float4*)tile;
    float4* dst = (float4*)(g_x1 + (size_t)(b * 32 + z) * (16 * 1152));
    for (int i = tid; i < 2304; i += 512) {
        int c = i % 9, r = i / 9;                      // r = ch*16 + yl2
        int yl2 = r & 15, ch = r >> 4;
        dst[ch * 288 + (yh * 16 + yl2) * 9 + c] = t4[r * 9 + c];
    }
}

// ---------- conv2 (16->32, 32^3 -> 16^3): 8 vox x 4 och, vector LDS (R14) ----------
__global__ void __launch_bounds__(128, 5) conv2_kernel(const float* __restrict__ b2) {
    extern __shared__ float tile[];                    // 16*17*40 = 10880 floats
    int tid = threadIdx.x;
    int bid = blockIdx.x;                              // 1024 = 32b*16z*2yh
    int yh = bid & 1, z = (bid >> 1) & 15, b = bid >> 5;
    int oh = tid & 7, xh = (tid >> 3) & 1, yl = tid >> 4;
    int ochb = oh * 4;
    int x0 = 8 * xh;

    float2 acc[8][2];
    {
        const float2* bb = (const float2*)b2;
        float2 c0 = bb[oh * 2], c1 = bb[oh * 2 + 1];
#pragma unroll
        for (int v = 0; v < 8; v++) { acc[v][0] = c0; acc[v][1] = c1; }
    }

    const float4* x1base = (const float4*)g_x1 + (size_t)(b * 32) * (16 * 32 * 9);

#pragma unroll 1
    for (int kz = 0; kz < 3; kz++) {
        int iz = 2 * z - 1 + kz;
        if ((unsigned)iz >= 32u) continue;
        __syncthreads();
        const float4* src = x1base + (size_t)iz * (16 * 32 * 9);
        for (int i = tid; i < 2448; i += 128) {
            int c = i % 9, r = i / 9;                  // r = ch*17 + iyl
            int iyl = r % 17, ch = r / 17;
            int iy = 16 * yh - 1 + iyl;
            float4 v = make_float4(0.f, 0.f, 0.f, 0.f);
            if ((unsigned)iy < 32u) v = src[(ch * 32 + iy) * 9 + c];
            ((float4*)tile)[r * 10 + c] = v;           // pitch 40 = 10 float4
        }
        __syncthreads();

#pragma unroll 1
        for (int ky = 0; ky < 3; ky++) {
            int iyl = 2 * yl + ky;
            const float* trb = tile + iyl * 40 + x0;
            const float* wb = g_w2p + (size_t)((kz * 3 + ky) * 3) * 512 + ochb;
#pragma unroll 2
            for (int in = 0; in < 16; in++) {
                const float* tr = trb + in * 680;      // 17*40
                float4 eA = *(const float4*)(tr);
                float4 eB = *(const float4*)(tr + 4);
                float4 oA = *(const float4*)(tr + 16);
                float4 oB = *(const float4*)(tr + 20);
                float  o8 = tr[24];
                const float* wp = wb + in * 32;
                float4 w0 = *(const float4*)(wp);          // kx=0
                float4 w1 = *(const float4*)(wp + 512);    // kx=1
                float4 w2v = *(const float4*)(wp + 1024);  // kx=2
                float2 w0a = make_float2(w0.x, w0.y),  w0b = make_float2(w0.z, w0.w);
                float2 w1a = make_float2(w1.x, w1.y),  w1b = make_float2(w1.z, w1.w);
                float2 w2a = make_float2(w2v.x, w2v.y), w2b = make_float2(w2v.z, w2v.w);
                float ev[8] = {eA.x, eA.y, eA.z, eA.w, eB.x, eB.y, eB.z, eB.w};
                float ov[9] = {oA.x, oA.y, oA.z, oA.w, oB.x, oB.y, oB.z, oB.w, o8};
#pragma unroll
                for (int v = 0; v < 8; v++) {
                    float2 ao = make_float2(ov[v], ov[v]);
                    float2 ae = make_float2(ev[v], ev[v]);
                    float2 a2 = make_float2(ov[v + 1], ov[v + 1]);
                    acc[v][0] = ffma2(ao, w0a, acc[v][0]);
                    acc[v][1] = ffma2(ao, w0b, acc[v][1]);
                    acc[v][0] = ffma2(ae, w1a, acc[v][0]);
                    acc[v][1] = ffma2(ae, w1b, acc[v][1]);
                    acc[v][0] = ffma2(a2, w2a, acc[v][0]);
                    acc[v][1] = ffma2(a2, w2b, acc[v][1]);
                }
            }
        }
    }

    int gy = yh * 8 + yl;
#pragma unroll
    for (int p = 0; p < 2; p++) {
#pragma unroll
        for (int comp = 0; comp < 2; comp++) {
            int c = ochb + 2 * p + comp;
            float r0 = fmaxf(comp ? acc[0][p].y : acc[0][p].x, 0.f);
            float r1 = fmaxf(comp ? acc[1][p].y : acc[1][p].x, 0.f);
            float r2 = fmaxf(comp ? acc[2][p].y : acc[2][p].x, 0.f);
            float r3 = fmaxf(comp ? acc[3][p].y : acc[3][p].x, 0.f);
            float r4 = fmaxf(comp ? acc[4][p].y : acc[4][p].x, 0.f);
            float r5 = fmaxf(comp ? acc[5][p].y : acc[5][p].x, 0.f);
            float r6 = fmaxf(comp ? acc[6][p].y : acc[6][p].x, 0.f);
            float r7 = fmaxf(comp ? acc[7][p].y : acc[7][p].x, 0.f);
            float* row = g_x2 + (((size_t)(b * 16 + z) * 32 + c) * 16 + gy) * 20;
            *(float4*)(row + 4 * xh) = make_float4(r0, r2, r4, r6);   // even x
            row[9 + 4 * xh]  = r1;                                    // odd x
            row[10 + 4 * xh] = r3;
            row[11 + 4 * xh] = r5;
            row[12 + 4 * xh] = r7;
            if (xh == 0) row[8] = 0.0f;                               // o[0] pad
        }
    }
}

// ---------- conv3 (32->64, 16^3 -> 8^3): x-split, 1024 blocks x 64 thr ----------
// block = (b, z8, yh2, xh2); 64 thr = oh16(minor) x yp4; thread = 4 vox x 4 och.
// tile [32ch][10iyl][12]: e[0..3] at 0, o[0..4] at 4..8, pad. 15.4KB.
__global__ void __launch_bounds__(64) conv3_kernel(const float* __restrict__ b3) {
    extern __shared__ float tile[];                    // 3840 floats
    int tid = threadIdx.x;
    int bid = blockIdx.x;                              // 1024 = 32b*8z*2yh*2xh
    int xh = bid & 1, yh = (bid >> 1) & 1, z = (bid >> 2) & 7, b = bid >> 5;
    int oh = tid & 15, yp = tid >> 4;                  // oh 0..15, yp 0..3
    int ochb = oh * 4;
    int xs = 4 * xh;

    float2 acc[4][2];
    {
        const float2* bb = (const float2*)b3;
        float2 c0 = bb[oh * 2], c1 = bb[oh * 2 + 1];
#pragma unroll
        for (int v = 0; v < 4; v++) { acc[v][0] = c0; acc[v][1] = c1; }
    }

    const float* x2b = g_x2 + (size_t)(b * 16) * (32 * 16 * 20);
    int iy0 = 8 * yh - 1;

#pragma unroll 1
    for (int kz = 0; kz < 3; kz++) {
        int iz = 2 * z - 1 + kz;
        if ((unsigned)iz >= 16u) continue;
        __syncthreads();
        const float* src = x2b + (size_t)iz * (32 * 16 * 20);
        for (int i = tid; i < 320; i += 64) {
            int iyl = i % 10, ch = i / 10;
            int iy = iy0 + iyl;
            float4 e = make_float4(0.f, 0.f, 0.f, 0.f);
            float4 o = make_float4(0.f, 0.f, 0.f, 0.f);
            float o4 = 0.f;
            if ((unsigned)iy < 16u) {
                const float* row = src + (size_t)(ch * 16 + iy) * 20;
                e  = *(const float4*)(row + xs);
                o  = *(const float4*)(row + 8 + xs);
                o4 = row[12 + xs];
            }
            float* t = tile + (ch * 10 + iyl) * 12;
            *(float4*)(t)     = e;
            *(float4*)(t + 4) = o;
            t[8] = o4;
        }
        __syncthreads();

#pragma unroll 1
        for (int ky = 0; ky < 3; ky++) {
            int iyl = 2 * yp + ky;                     // 0..9
            const float* trb = tile + iyl * 12;
            const float* wb = g_w3p + (size_t)((kz * 3 + ky) * 3) * 2048 + ochb;
#pragma unroll 4
            for (int in = 0; in < 32; in++) {
                const float* tr = trb + in * 120;
                float4 e  = *(const float4*)(tr);
                float4 oa = *(const float4*)(tr + 4);
                float  o4 = tr[8];
                const float* wp = wb + in * 64;
                float4 w0 = *(const float4*)(wp);           // kx=0
                float4 w1 = *(const float4*)(wp + 2048);    // kx=1
                float4 w2v = *(const float4*)(wp + 4096);   // kx=2
                float2 w0a = make_float2(w0.x, w0.y),  w0b = make_float2(w0.z, w0.w);
                float2 w1a = make_float2(w1.x, w1.y),  w1b = make_float2(w1.z, w1.w);
                float2 w2a = make_float2(w2v.x, w2v.y), w2b = make_float2(w2v.z, w2v.w);
                float ev[4] = {e.x, e.y, e.z, e.w};
                float ov[5] = {oa.x, oa.y, oa.z, oa.w, o4};
#pragma unroll
                for (int v = 0; v < 4; v++) {
                    float2 ao = make_float2(ov[v], ov[v]);
                    float2 ae = make_float2(ev[v], ev[v]);
                    float2 a2 = make_float2(ov[v + 1], ov[v + 1]);
                    acc[v][0] = ffma2(ao, w0a, acc[v][0]);
                    acc[v][1] = ffma2(ao, w0b, acc[v][1]);
                    acc[v][0] = ffma2(ae, w1a, acc[v][0]);
                    acc[v][1] = ffma2(ae, w1b, acc[v][1]);
                    acc[v][0] = ffma2(a2, w2a, acc[v][0]);
                    acc[v][1] = ffma2(a2, w2b, acc[v][1]);
                }
            }
        }
    }

    // writeout: feat [b][c*512 + s], 4 contiguous x per och: STG.128
    int y = yh * 4 + yp;
    int s0 = z * 64 + y * 8 + xs;
    float* fb = g_feat + (size_t)b * 32768;
#pragma unroll
    for (int p = 0; p < 2; p++) {
#pragma unroll
        for (int comp = 0; comp < 2; comp++) {
            int c = ochb + 2 * p + comp;
            float r0 = fmaxf(comp ? acc[0][p].y : acc[0][p].x, 0.f);
            float r1 = fmaxf(comp ? acc[1][p].y : acc[1][p].x, 0.f);
            float r2 = fmaxf(comp ? acc[2][p].y : acc[2][p].x, 0.f);
            float r3 = fmaxf(comp ? acc[3][p].y : acc[3][p].x, 0.f);
            *(float4*)(fb + (size_t)c * 512 + s0) = make_float4(r0, r1, r2, r3);
        }
    }
}

// ---------- FC (32 x 128 <- 32768), 128 blocks ----------
__global__ void fc_kernel(const float* __restrict__ fcw, const float* __restrict__ fcb,
                          float* __restrict__ out) {
    int t = threadIdx.x;
    int bg = blockIdx.x;                                // 0..7
    int lc = blockIdx.y;                                // 0..15
    int fl = t & 127;
    int bq = t >> 7;                                    // 0..3
    int l0 = lc * 8;
    int b = bg * 4 + bq;

    float acc[8] = {0.f, 0.f, 0.f, 0.f, 0.f, 0.f, 0.f, 0.f};

    const float4* fw4 = (const float4*)fcw;
    const float4* ft4 = (const float4*)g_feat + (size_t)b * 8192;
#pragma unroll 2
    for (int i = 0; i < 64; i++) {
        int k = fl + 128 * i;
        float4 f = ft4[k];
#pragma unroll
        for (int j = 0; j < 8; j++) {
            float4 w = fw4[(size_t)(l0 + j) * 8192 + k];
            acc[j] += f.x * w.x + f.y * w.y + f.z * w.z + f.w * w.w;
        }
    }
#pragma unroll
    for (int j = 0; j < 8; j++) {
        float v = acc[j];
        for (int off = 16; off > 0; off >>= 1) v += __shfl_xor_sync(0xffffffffu, v, off);
        acc[j] = v;
    }

    __shared__ float sh[16 * 8];
    int warp = t >> 5, lane = t & 31;
    if (lane < 8) sh[warp * 8 + lane] = acc[lane];
    __syncthreads();
    if (t < 32) {
        int bq2 = t >> 3, j = t & 7;
        float s = sh[(bq2 * 4 + 0) * 8 + j] + sh[(bq2 * 4 + 1) * 8 + j] +
                  sh[(bq2 * 4 + 2) * 8 + j] + sh[(bq2 * 4 + 3) * 8 + j];
        out[(size_t)(bg * 4 + bq2) * 128 + l0 + j] = s + fcb[l0 + j];
    }
}

// ---------- launch (conv2 at kernel index 3 for ncu capture) ----------
extern "C" void kernel_launch(void* const* d_in, const int* in_sizes, int n_in,
                              void* d_out, int out_size) {
    (void)in_sizes; (void)n_in; (void)out_size;
    const float* pc  = (const float*)d_in[0];
    const float* w1  = (const float*)d_in[1];
    const float* b1  = (const float*)d_in[2];
    const float* w2  = (const float*)d_in[3];
    const float* b2  = (const float*)d_in[4];
    const float* w3  = (const float*)d_in[5];
    const float* b3  = (const float*)d_in[6];
    const float* fcw = (const float*)d_in[7];
    const float* fcb = (const float*)d_in[8];
    float* out = (float*)d_out;

    cudaFuncSetAttribute(conv2_kernel, cudaFuncAttributeMaxDynamicSharedMemorySize, 43520);
    cudaFuncSetAttribute(conv3_kernel, cudaFuncAttributeMaxDynamicSharedMemorySize, 15360);

    clear_and_repack<<<256, 256>>>(w2, w3);    // k0
    scatter_kernel<<<2048, 256>>>(pc);         // k1
    conv1_kernel<<<2048, 512>>>(w1, b1);       // k2
    conv2_kernel<<<1024, 128, 43520>>>(b2);    // k3 -> profiled
    conv3_kernel<<<1024, 64, 15360>>>(b3);     // k4
    fc_kernel<<<dim3(8, 16), 512>>>(fcw, fcb, out);  // k5
}

// round 17
// speedup vs baseline: 1.0735x; 1.0735x over previous
#include <cuda_runtime.h>
#include <cstring>

#define DINLINE __device__ __forceinline__

DINLINE float2 ffma2(float2 a, float2 b, float2 c) {
    unsigned long long au, bu, cu, ru;
    memcpy(&au, &a, 8); memcpy(&bu, &b, 8); memcpy(&cu, &c, 8);
    asm("fma.rn.f32x2 %0, %1, %2, %3;" : "=l"(ru) : "l"(au), "l"(bu), "l"(cu));
    float2 r; memcpy(&r, &ru, 8); return r;
}
DINLINE float2 fadd2(float2 a, float2 b) {
    unsigned long long au, bu, ru;
    memcpy(&au, &a, 8); memcpy(&bu, &b, 8);
    asm("add.rn.f32x2 %0, %1, %2;" : "=l"(ru) : "l"(au), "l"(bu));
    float2 r; memcpy(&r, &ru, 8); return r;
}

// ---------- scratch ----------
__device__ unsigned long long g_grid64[32 * 64 * 64];            // 1 MB bitmask
// x1: [b][iz32][ch16][iy32][36]  even x(16) 0..15, odd_shifted(17) 16..32, pad
__device__ float g_x1[(size_t)32 * 32 * 16 * 32 * 36];           // 75.5 MB
// x2: [b][iz16][ch32][iy16][20]  even x(8) 0..7, odd_shifted(9) 8..16, pad
__device__ float g_x2[(size_t)32 * 16 * 32 * 16 * 20];           // 21 MB
__device__ float g_feat[(size_t)32 * 32768];                     // [b][c*512 + s]
__device__ float g_w2p[27 * 16 * 32];                            // [tap][in][och]
__device__ float g_w3p[27 * 32 * 64];                            // [tap][in][och]

// ---------- fused: clear grid + repack w2 + repack w3 ----------
__global__ void clear_and_repack(const float* __restrict__ w2,
                                 const float* __restrict__ w3) {
    int i = blockIdx.x * 256 + threadIdx.x;            // 65536 threads
    ((ulonglong2*)g_grid64)[i] = make_ulonglong2(0ull, 0ull);
    if (i < 13824) {
        int tap = i % 27; int r = i / 27;
        int in = r % 16;  int och = r / 16;
        g_w2p[(tap * 16 + in) * 32 + och] = w2[i];
    }
    if (i < 55296) {
        int tap = i % 27; int r = i / 27;
        int in = r % 32;  int och = r / 32;
        g_w3p[(tap * 32 + in) * 64 + och] = w3[i];
    }
}

__global__ void scatter_kernel(const float* __restrict__ pc) {
    int t = blockIdx.x * 256 + threadIdx.x;            // 524288
    float px = pc[t * 3 + 0];
    float py = pc[t * 3 + 1];
    float pz = pc[t * 3 + 2];
    int b = t >> 14;
    int cx = (int)(((px + 1.0f) * 0.5f) * 63.0f); cx = min(max(cx, 0), 63);
    int cy = (int)(((py + 1.0f) * 0.5f) * 63.0f); cy = min(max(cy, 0), 63);
    int cz = (int)(((pz + 1.0f) * 0.5f) * 63.0f); cz = min(max(cz, 0), 63);
    atomicOr(&g_grid64[(b * 64 + cz) * 64 + cy], 1ull << cx);
}

// ---------- conv1 (1->16, 64^3 -> 32^3) ----------
__global__ void __launch_bounds__(512) conv1_kernel(const float* __restrict__ w1,
                                                    const float* __restrict__ b1) {
    __shared__ float2 sw[27 * 8];
    __shared__ float2 sb[8];
    __shared__ float tile[16 * 16 * 36];               // 36.9 KB
    int tid = threadIdx.x;
    int bid = blockIdx.x;                              // 2048 = 32b*32z*2yh
    int yh = bid & 1, z = (bid >> 1) & 31, b = bid >> 6;

    for (int j = tid; j < 216; j += 512) {
        int cp = j & 7, tap = j >> 3;
        sw[j] = make_float2(w1[(2 * cp) * 27 + tap], w1[(2 * cp + 1) * 27 + tap]);
    }
    if (tid < 8) sb[tid] = make_float2(b1[2 * tid], b1[2 * tid + 1]);
    __syncthreads();

    int x = tid & 31, yl = tid >> 5;
    int y = yh * 16 + yl;

    float2 acc[8];
#pragma unroll
    for (int j = 0; j < 8; j++) acc[j] = sb[j];

#pragma unroll 1
    for (int kz = 0; kz < 3; kz++) {
        int iz = 2 * z - 1 + kz;
        if ((unsigned)iz >= 64u) continue;
#pragma unroll 1
        for (int ky = 0; ky < 3; ky++) {
            int iy = 2 * y - 1 + ky;
            if ((unsigned)iy >= 64u) continue;
            unsigned long long m = g_grid64[(b * 64 + iz) * 64 + iy];
            if (!m) continue;
            int tapb = (kz * 3 + ky) * 3;
#pragma unroll 1
            for (int kx = 0; kx < 3; kx++) {
                int ix = 2 * x - 1 + kx;
                if ((unsigned)ix < 64u && ((m >> ix) & 1ull)) {
                    const float2* wv = &sw[(tapb + kx) * 8];
#pragma unroll
                    for (int j = 0; j < 8; j++) acc[j] = fadd2(acc[j], wv[j]);
                }
            }
        }
    }
    int off = (x & 1) ? (16 + ((x + 1) >> 1)) : (x >> 1);
    float* trow = tile + yl * 36;
#pragma unroll
    for (int j = 0; j < 8; j++) {
        trow[(2 * j) * 576 + off]     = fmaxf(acc[j].x, 0.0f);
        trow[(2 * j + 1) * 576 + off] = fmaxf(acc[j].y, 0.0f);
    }
    if (x == 0) {
#pragma unroll
        for (int ch = 0; ch < 16; ch++) trow[ch * 576 + 16] = 0.0f;   // odd_s[0]
    }
    __syncthreads();

    const float4* t4 = (const float4*)tile;
    float4* dst = (float4*)(g_x1 + (size_t)(b * 32 + z) * (16 * 1152));
    for (int i = tid; i < 2304; i += 512) {
        int c = i % 9, r = i / 9;                      // r = ch*16 + yl2
        int yl2 = r & 15, ch = r >> 4;
        dst[ch * 288 + (yh * 16 + yl2) * 9 + c] = t4[r * 9 + c];
    }
}

// ---------- conv2 (16->32, 32^3 -> 16^3): 8 vox x 4 och, vector LDS (R14) ----------
__global__ void __launch_bounds__(128, 5) conv2_kernel(const float* __restrict__ b2) {
    extern __shared__ float tile[];                    // 16*17*40 = 10880 floats
    int tid = threadIdx.x;
    int bid = blockIdx.x;                              // 1024 = 32b*16z*2yh
    int yh = bid & 1, z = (bid >> 1) & 15, b = bid >> 5;
    int oh = tid & 7, xh = (tid >> 3) & 1, yl = tid >> 4;
    int ochb = oh * 4;
    int x0 = 8 * xh;

    float2 acc[8][2];
    {
        const float2* bb = (const float2*)b2;
        float2 c0 = bb[oh * 2], c1 = bb[oh * 2 + 1];
#pragma unroll
        for (int v = 0; v < 8; v++) { acc[v][0] = c0; acc[v][1] = c1; }
    }

    const float4* x1base = (const float4*)g_x1 + (size_t)(b * 32) * (16 * 32 * 9);

#pragma unroll 1
    for (int kz = 0; kz < 3; kz++) {
        int iz = 2 * z - 1 + kz;
        if ((unsigned)iz >= 32u) continue;
        __syncthreads();
        const float4* src = x1base + (size_t)iz * (16 * 32 * 9);
        for (int i = tid; i < 2448; i += 128) {
            int c = i % 9, r = i / 9;                  // r = ch*17 + iyl
            int iyl = r % 17, ch = r / 17;
            int iy = 16 * yh - 1 + iyl;
            float4 v = make_float4(0.f, 0.f, 0.f, 0.f);
            if ((unsigned)iy < 32u) v = src[(ch * 32 + iy) * 9 + c];
            ((float4*)tile)[r * 10 + c] = v;           // pitch 40 = 10 float4
        }
        __syncthreads();

#pragma unroll 1
        for (int ky = 0; ky < 3; ky++) {
            int iyl = 2 * yl + ky;
            const float* trb = tile + iyl * 40 + x0;
            const float* wb = g_w2p + (size_t)((kz * 3 + ky) * 3) * 512 + ochb;
#pragma unroll 2
            for (int in = 0; in < 16; in++) {
                const float* tr = trb + in * 680;      // 17*40
                float4 eA = *(const float4*)(tr);
                float4 eB = *(const float4*)(tr + 4);
                float4 oA = *(const float4*)(tr + 16);
                float4 oB = *(const float4*)(tr + 20);
                float  o8 = tr[24];
                const float* wp = wb + in * 32;
                float4 w0 = *(const float4*)(wp);          // kx=0
                float4 w1 = *(const float4*)(wp + 512);    // kx=1
                float4 w2v = *(const float4*)(wp + 1024);  // kx=2
                float2 w0a = make_float2(w0.x, w0.y),  w0b = make_float2(w0.z, w0.w);
                float2 w1a = make_float2(w1.x, w1.y),  w1b = make_float2(w1.z, w1.w);
                float2 w2a = make_float2(w2v.x, w2v.y), w2b = make_float2(w2v.z, w2v.w);
                float ev[8] = {eA.x, eA.y, eA.z, eA.w, eB.x, eB.y, eB.z, eB.w};
                float ov[9] = {oA.x, oA.y, oA.z, oA.w, oB.x, oB.y, oB.z, oB.w, o8};
#pragma unroll
                for (int v = 0; v < 8; v++) {
                    float2 ao = make_float2(ov[v], ov[v]);
                    float2 ae = make_float2(ev[v], ev[v]);
                    float2 a2 = make_float2(ov[v + 1], ov[v + 1]);
                    acc[v][0] = ffma2(ao, w0a, acc[v][0]);
                    acc[v][1] = ffma2(ao, w0b, acc[v][1]);
                    acc[v][0] = ffma2(ae, w1a, acc[v][0]);
                    acc[v][1] = ffma2(ae, w1b, acc[v][1]);
                    acc[v][0] = ffma2(a2, w2a, acc[v][0]);
                    acc[v][1] = ffma2(a2, w2b, acc[v][1]);
                }
            }
        }
    }

    int gy = yh * 8 + yl;
#pragma unroll
    for (int p = 0; p < 2; p++) {
#pragma unroll
        for (int comp = 0; comp < 2; comp++) {
            int c = ochb + 2 * p + comp;
            float r0 = fmaxf(comp ? acc[0][p].y : acc[0][p].x, 0.f);
            float r1 = fmaxf(comp ? acc[1][p].y : acc[1][p].x, 0.f);
            float r2 = fmaxf(comp ? acc[2][p].y : acc[2][p].x, 0.f);
            float r3 = fmaxf(comp ? acc[3][p].y : acc[3][p].x, 0.f);
            float r4 = fmaxf(comp ? acc[4][p].y : acc[4][p].x, 0.f);
            float r5 = fmaxf(comp ? acc[5][p].y : acc[5][p].x, 0.f);
            float r6 = fmaxf(comp ? acc[6][p].y : acc[6][p].x, 0.f);
            float r7 = fmaxf(comp ? acc[7][p].y : acc[7][p].x, 0.f);
            float* row = g_x2 + (((size_t)(b * 16 + z) * 32 + c) * 16 + gy) * 20;
            *(float4*)(row + 4 * xh) = make_float4(r0, r2, r4, r6);   // even x
            row[9 + 4 * xh]  = r1;                                    // odd x
            row[10 + 4 * xh] = r3;
            row[11 + 4 * xh] = r5;
            row[12 + 4 * xh] = r7;
            if (xh == 0) row[8] = 0.0f;                               // o[0] pad
        }
    }
}

// ---------- conv3 (32->64, 16^3 -> 8^3): 512 blocks x 128 thr, proven tile ----------
// block = (b, z8, yh2); 128 thr = oh16(minor) x xh2 x yp4; thread = 4 vox x 4 och.
// tile [32ch][10iyl][20] = 25.6KB (R12 staging, float4-coalesced).
__global__ void __launch_bounds__(128, 4) conv3_kernel(const float* __restrict__ b3) {
    extern __shared__ float tile[];                    // 6400 floats
    int tid = threadIdx.x;
    int bid = blockIdx.x;                              // 512 = 32b*8z*2yh
    int yh = bid & 1, z = (bid >> 1) & 7, b = bid >> 4;
    int oh = tid & 15, xh = (tid >> 4) & 1, yp = tid >> 5;   // oh 0..15, yp 0..3
    int ochb = oh * 4;
    int xs = 4 * xh;

    float2 acc[4][2];
    {
        const float2* bb = (const float2*)b3;
        float2 c0 = bb[oh * 2], c1 = bb[oh * 2 + 1];
#pragma unroll
        for (int v = 0; v < 4; v++) { acc[v][0] = c0; acc[v][1] = c1; }
    }

    const float4* x2base = (const float4*)g_x2 + (size_t)(b * 16) * (32 * 16 * 5);
    int iy0 = 8 * yh - 1;

#pragma unroll 1
    for (int kz = 0; kz < 3; kz++) {
        int iz = 2 * z - 1 + kz;
        if ((unsigned)iz >= 16u) continue;
        __syncthreads();
        const float4* src = x2base + (size_t)iz * (32 * 16 * 5);
        for (int i = tid; i < 1600; i += 128) {
            int c = i % 5, r = i / 5;                  // r = ch*10 + iyl
            int iyl = r % 10, ch = r / 10;
            int iy = iy0 + iyl;
            float4 v = make_float4(0.f, 0.f, 0.f, 0.f);
            if ((unsigned)iy < 16u) v = src[(ch * 16 + iy) * 5 + c];
            ((float4*)tile)[r * 5 + c] = v;
        }
        __syncthreads();

#pragma unroll 1
        for (int ky = 0; ky < 3; ky++) {
            int iyl = 2 * yp + ky;                     // 0..9
            const float* trb = tile + iyl * 20;
            const float* wb = g_w3p + (size_t)((kz * 3 + ky) * 3) * 2048 + ochb;
#pragma unroll 4
            for (int in = 0; in < 32; in++) {
                const float* tr = trb + in * 200;
                float4 e  = *(const float4*)(tr + xs);          // e[4xh..4xh+3]
                float4 oa = *(const float4*)(tr + 8 + xs);      // o[4xh..4xh+3]
                float  o4 = tr[12 + xs];                        // o[4xh+4]
                const float* wp = wb + in * 64;
                float4 w0 = *(const float4*)(wp);           // kx=0
                float4 w1 = *(const float4*)(wp + 2048);    // kx=1
                float4 w2v = *(const float4*)(wp + 4096);   // kx=2
                float2 w0a = make_float2(w0.x, w0.y),  w0b = make_float2(w0.z, w0.w);
                float2 w1a = make_float2(w1.x, w1.y),  w1b = make_float2(w1.z, w1.w);
                float2 w2a = make_float2(w2v.x, w2v.y), w2b = make_float2(w2v.z, w2v.w);
                float ev[4] = {e.x, e.y, e.z, e.w};
                float ov[5] = {oa.x, oa.y, oa.z, oa.w, o4};
#pragma unroll
                for (int v = 0; v < 4; v++) {
                    float2 ao = make_float2(ov[v], ov[v]);
                    float2 ae = make_float2(ev[v], ev[v]);
                    float2 a2 = make_float2(ov[v + 1], ov[v + 1]);
                    acc[v][0] = ffma2(ao, w0a, acc[v][0]);
                    acc[v][1] = ffma2(ao, w0b, acc[v][1]);
                    acc[v][0] = ffma2(ae, w1a, acc[v][0]);
                    acc[v][1] = ffma2(ae, w1b, acc[v][1]);
                    acc[v][0] = ffma2(a2, w2a, acc[v][0]);
                    acc[v][1] = ffma2(a2, w2b, acc[v][1]);
                }
            }
        }
    }

    // writeout: feat [b][c*512 + s], STG.128 per och
    int y = yh * 4 + yp;
    int s0 = z * 64 + y * 8 + xs;
    float* fb = g_feat + (size_t)b * 32768;
#pragma unroll
    for (int p = 0; p < 2; p++) {
#pragma unroll
        for (int comp = 0; comp < 2; comp++) {
            int c = ochb + 2 * p + comp;
            float r0 = fmaxf(comp ? acc[0][p].y : acc[0][p].x, 0.f);
            float r1 = fmaxf(comp ? acc[1][p].y : acc[1][p].x, 0.f);
            float r2 = fmaxf(comp ? acc[2][p].y : acc[2][p].x, 0.f);
            float r3 = fmaxf(comp ? acc[3][p].y : acc[3][p].x, 0.f);
            *(float4*)(fb + (size_t)c * 512 + s0) = make_float4(r0, r1, r2, r3);
        }
    }
}

// ---------- FC (32 x 128 <- 32768), 128 blocks ----------
__global__ void fc_kernel(const float* __restrict__ fcw, const float* __restrict__ fcb,
                          float* __restrict__ out) {
    int t = threadIdx.x;
    int bg = blockIdx.x;                                // 0..7
    int lc = blockIdx.y;                                // 0..15
    int fl = t & 127;
    int bq = t >> 7;                                    // 0..3
    int l0 = lc * 8;
    int b = bg * 4 + bq;

    float acc[8] = {0.f, 0.f, 0.f, 0.f, 0.f, 0.f, 0.f, 0.f};

    const float4* fw4 = (const float4*)fcw;
    const float4* ft4 = (const float4*)g_feat + (size_t)b * 8192;
#pragma unroll 2
    for (int i = 0; i < 64; i++) {
        int k = fl + 128 * i;
        float4 f = ft4[k];
#pragma unroll
        for (int j = 0; j < 8; j++) {
            float4 w = fw4[(size_t)(l0 + j) * 8192 + k];
            acc[j] += f.x * w.x + f.y * w.y + f.z * w.z + f.w * w.w;
        }
    }
#pragma unroll
    for (int j = 0; j < 8; j++) {
        float v = acc[j];
        for (int off = 16; off > 0; off >>= 1) v += __shfl_xor_sync(0xffffffffu, v, off);
        acc[j] = v;
    }

    __shared__ float sh[16 * 8];
    int warp = t >> 5, lane = t & 31;
    if (lane < 8) sh[warp * 8 + lane] = acc[lane];
    __syncthreads();
    if (t < 32) {
        int bq2 = t >> 3, j = t & 7;
        float s = sh[(bq2 * 4 + 0) * 8 + j] + sh[(bq2 * 4 + 1) * 8 + j] +
                  sh[(bq2 * 4 + 2) * 8 + j] + sh[(bq2 * 4 + 3) * 8 + j];
        out[(size_t)(bg * 4 + bq2) * 128 + l0 + j] = s + fcb[l0 + j];
    }
}

// ---------- launch (conv2 at kernel index 3 for ncu capture) ----------
extern "C" void kernel_launch(void* const* d_in, const int* in_sizes, int n_in,
                              void* d_out, int out_size) {
    (void)in_sizes; (void)n_in; (void)out_size;
    const float* pc  = (const float*)d_in[0];
    const float* w1  = (const float*)d_in[1];
    const float* b1  = (const float*)d_in[2];
    const float* w2  = (const float*)d_in[3];
    const float* b2  = (const float*)d_in[4];
    const float* w3  = (const float*)d_in[5];
    const float* b3  = (const float*)d_in[6];
    const float* fcw = (const float*)d_in[7];
    const float* fcb = (const float*)d_in[8];
    float* out = (float*)d_out;

    cudaFuncSetAttribute(conv2_kernel, cudaFuncAttributeMaxDynamicSharedMemorySize, 43520);
    cudaFuncSetAttribute(conv3_kernel, cudaFuncAttributeMaxDynamicSharedMemorySize, 25600);

    clear_and_repack<<<256, 256>>>(w2, w3);    // k0
    scatter_kernel<<<2048, 256>>>(pc);         // k1
    conv1_kernel<<<2048, 512>>>(w1, b1);       // k2
    conv2_kernel<<<1024, 128, 43520>>>(b2);    // k3 -> profiled
    conv3_kernel<<<512, 128, 25600>>>(b3);     // k4
    fc_kernel<<<dim3(8, 16), 512>>>(fcw, fcb, out);  // k5
}